// round 6
// baseline (speedup 1.0000x reference)
#include <cuda_runtime.h>
#include <cstdint>

// Problem dims
#define PD1   128
#define PD2   128
#define PB    16
#define PSIN  64
#define PSOUT 128
// a / h layout: [i][j][b][s] row-major, s fastest.
// float offset = i*262144 + j*2048 + b*128 + s

typedef unsigned long long ull_t;

__device__ __forceinline__ void ffma2(ull_t &d, ull_t a, ull_t b) {
    asm("fma.rn.f32x2 %0, %1, %2, %0;" : "+l"(d) : "l"(a), "l"(b));
}
__device__ __forceinline__ float tanh_fast(float z) {
    // tanh(z) = 1 - 2/(exp(2z)+1) via MUFU ex2 + rcp (err ~1e-6)
    float e;
    asm("ex2.approx.f32 %0, %1;" : "=f"(e) : "f"(z * 2.8853900817779268f));
    float rc;
    asm("rcp.approx.f32 %0, %1;" : "=f"(rc) : "f"(e + 1.0f));
    return fmaf(-2.0f, rc, 1.0f);
}

// ---------------- Kernel 1: a = x @ w + bias  (into d_out) ----------------
// Block tile 128m x 128n, 256 threads, micro-tile 8m x 8n (4 f32x2 segs).
// x stored in smem PRE-DUPLICATED as (x,x) 64-bit pairs -> inner loop is pure
// LDS.64 + FFMA2 (no pack movs). K=64 in four 16-wide phases (24KB smem).
#define KP 16
__global__ __launch_bounds__(256)
void mdrnn_gemm_kernel(const float* __restrict__ X, const float* __restrict__ W,
                       const float* __restrict__ Bias, float* __restrict__ A) {
    __shared__ ull_t xs2[128 * KP];   // 16384 B, row stride 128B
    __shared__ float ws[KP * 128];    //  8192 B

    const int tid   = threadIdx.x;
    const int mtile = blockIdx.x;                 // 2048 tiles of 128 rows
    const float* Xb = X + (size_t)mtile * 128 * PSIN;

    const int tidm = tid >> 4;        // 0..15  -> m0 = tidm*8
    const int tidn = tid & 15;        // 0..15  -> n  = tidn*2 + seg*32
    const int m0   = tidm * 8;
    const int n0   = tidn * 2;

    ull_t acc[8][4];
#pragma unroll
    for (int mi = 0; mi < 8; mi++)
#pragma unroll
        for (int seg = 0; seg < 4; seg++) acc[mi][seg] = 0ULL;

    for (int kk = 0; kk < PSIN; kk += KP) {
        __syncthreads();
        // x phase-tile: 128 rows x 16 k = 512 float4, 2 per thread; dup-store
#pragma unroll
        for (int q = 0; q < 2; q++) {
            int id  = tid + 256 * q;
            int row = id >> 2;        // 0..127
            int kq  = id & 3;         // float4 index within 16 k
            float4 v = *(const float4*)(Xb + row * PSIN + kk + kq * 4);
            ull_t* p = &xs2[row * KP + kq * 4];
            unsigned int ax = __float_as_uint(v.x), ay = __float_as_uint(v.y);
            unsigned int az = __float_as_uint(v.z), aw = __float_as_uint(v.w);
            ull_t d0, d1, d2, d3;
            asm("mov.b64 %0, {%1, %1};" : "=l"(d0) : "r"(ax));
            asm("mov.b64 %0, {%1, %1};" : "=l"(d1) : "r"(ay));
            asm("mov.b64 %0, {%1, %1};" : "=l"(d2) : "r"(az));
            asm("mov.b64 %0, {%1, %1};" : "=l"(d3) : "r"(aw));
            p[0] = d0; p[1] = d1; p[2] = d2; p[3] = d3;
        }
        // w phase-tile: 16 k x 128 n = 512 float4, 2 per thread
#pragma unroll
        for (int q = 0; q < 2; q++) {
            int id = tid + 256 * q;
            int k  = id >> 5;
            int nq = id & 31;
            *(float4*)&ws[k * 128 + nq * 4] =
                *(const float4*)(W + (size_t)(kk + k) * PSOUT + nq * 4);
        }
        __syncthreads();

#pragma unroll
        for (int k = 0; k < KP; k++) {
            ull_t wv[4];
#pragma unroll
            for (int seg = 0; seg < 4; seg++)
                wv[seg] = *(const ull_t*)&ws[k * 128 + n0 + seg * 32];
#pragma unroll
            for (int mi = 0; mi < 8; mi++) {
                ull_t xp = xs2[(m0 + mi) * KP + k];
#pragma unroll
                for (int seg = 0; seg < 4; seg++) ffma2(acc[mi][seg], xp, wv[seg]);
            }
        }
    }

    float2 bv[4];
#pragma unroll
    for (int seg = 0; seg < 4; seg++)
        bv[seg] = *(const float2*)(Bias + n0 + seg * 32);

#pragma unroll
    for (int mi = 0; mi < 8; mi++) {
        float* out = A + ((size_t)mtile * 128 + m0 + mi) * PSOUT;
#pragma unroll
        for (int seg = 0; seg < 4; seg++) {
            uint2 u = *(uint2*)&acc[mi][seg];
            float2 o;
            o.x = __uint_as_float(u.x) + bv[seg].x;
            o.y = __uint_as_float(u.y) + bv[seg].y;
            *(float2*)(out + n0 + seg * 32) = o;
        }
    }
}

// ---------------- Kernel 2: warp-synchronous wavefront scan ----------------
// One warp per (b, 8-wide s chunk): 256 blocks x 32 threads, NO __syncthreads.
// Rows on lanes (4 strips of 32), diagonal skew inside the warp:
//   at iter t, lane l handles j = t - l; h[i-1][j] arrives via __shfl_up of
//   the value lane l-1 computed at iter t-1 (its j was t-1-(l-1) = t-l).
// Strip boundary row (lane 31) handed to next strip's lane 0 via smem.
//
// Prefetch ring (depth 8): slot (t & 7) is consumed at iter t (j = t - lane)
// and refilled at iter t with jf = t + 8 - lane (consumed at t + 8).
// CRITICAL: the refill is INDEPENDENT of this iteration's activity — it is
// guarded only by 0 <= jf < 128. (R5 bug: refill inside the j-guard left
// slots consumed at t in [8-lane .. lane+7] uninitialized.)
#define SDEPTH 8
__global__ __launch_bounds__(32)
void mdrnn_scan_kernel(const float* __restrict__ U, float* __restrict__ H) {
    __shared__ float4 buf[128][2];    // h[strip_end][j][s0..s0+7], 4KB

    const int lane = threadIdx.x;
    const int b    = blockIdx.x >> 4;     // 0..15
    const int sc   = blockIdx.x & 15;     // 0..15
    const int s0   = sc * 8;

    const float4 u0a = *(const float4*)(U + s0);
    const float4 u0b = *(const float4*)(U + s0 + 4);
    const float4 u1a = *(const float4*)(U + PSOUT + s0);
    const float4 u1b = *(const float4*)(U + PSOUT + s0 + 4);

    const size_t base_bs = (size_t)b * PSOUT + s0;

    for (int ss = 0; ss < 4; ss++) {
        const int row = ss * 32 + lane;
        float* Hrow = H + (size_t)row * 262144 + base_bs;   // + j*2048

        // seed: slot q <- a[j = q - lane] (consumed at t = q), valid j only
        float4 ra[SDEPTH], rb[SDEPTH];
#pragma unroll
        for (int q = 0; q < SDEPTH; q++) {
            int j = q - lane;
            if ((unsigned)j < 128u) {
                ra[q] = *(const float4*)(Hrow + (size_t)j * 2048);
                rb[q] = *(const float4*)(Hrow + (size_t)j * 2048 + 4);
            }
        }

        float4 ha = make_float4(0.f, 0.f, 0.f, 0.f);   // h of this lane, prev iter
        float4 hb = make_float4(0.f, 0.f, 0.f, 0.f);

        for (int t = 0; t < 159; t++) {
            // cross-lane handoff of previous iteration's h (all lanes converged)
            float4 pa, pb;
            pa.x = __shfl_up_sync(0xffffffffu, ha.x, 1);
            pa.y = __shfl_up_sync(0xffffffffu, ha.y, 1);
            pa.z = __shfl_up_sync(0xffffffffu, ha.z, 1);
            pa.w = __shfl_up_sync(0xffffffffu, ha.w, 1);
            pb.x = __shfl_up_sync(0xffffffffu, hb.x, 1);
            pb.y = __shfl_up_sync(0xffffffffu, hb.y, 1);
            pb.z = __shfl_up_sync(0xffffffffu, hb.z, 1);
            pb.w = __shfl_up_sync(0xffffffffu, hb.w, 1);

            const int  j    = t - lane;
            const int  slot = t & (SDEPTH - 1);

            // consume slot, then refill it unconditionally-on-activity
            float4 aa = ra[slot], ab = rb[slot];
            int jf = t + SDEPTH - lane;
            if ((unsigned)jf < 128u) {
                ra[slot] = *(const float4*)(Hrow + (size_t)jf * 2048);
                rb[slot] = *(const float4*)(Hrow + (size_t)jf * 2048 + 4);
            }

            if ((unsigned)j < 128u) {
                float4 qa, qb;   // h[row-1][j]
                if (lane == 0) {
                    if (ss == 0) {
                        qa = make_float4(0.f, 0.f, 0.f, 0.f);
                        qb = make_float4(0.f, 0.f, 0.f, 0.f);
                    } else {
                        qa = buf[j][0];
                        qb = buf[j][1];
                    }
                } else {
                    qa = pa; qb = pb;
                }

                float4 za, zb;
                za.x = fmaf(qa.x, u0a.x, aa.x); za.x = fmaf(ha.x, u1a.x, za.x);
                za.y = fmaf(qa.y, u0a.y, aa.y); za.y = fmaf(ha.y, u1a.y, za.y);
                za.z = fmaf(qa.z, u0a.z, aa.z); za.z = fmaf(ha.z, u1a.z, za.z);
                za.w = fmaf(qa.w, u0a.w, aa.w); za.w = fmaf(ha.w, u1a.w, za.w);
                zb.x = fmaf(qb.x, u0b.x, ab.x); zb.x = fmaf(hb.x, u1b.x, zb.x);
                zb.y = fmaf(qb.y, u0b.y, ab.y); zb.y = fmaf(hb.y, u1b.y, zb.y);
                zb.z = fmaf(qb.z, u0b.z, ab.z); zb.z = fmaf(hb.z, u1b.z, zb.z);
                zb.w = fmaf(qb.w, u0b.w, ab.w); zb.w = fmaf(hb.w, u1b.w, zb.w);

                ha.x = tanh_fast(za.x); ha.y = tanh_fast(za.y);
                ha.z = tanh_fast(za.z); ha.w = tanh_fast(za.w);
                hb.x = tanh_fast(zb.x); hb.y = tanh_fast(zb.y);
                hb.z = tanh_fast(zb.z); hb.w = tanh_fast(zb.w);

                *(float4*)(Hrow + (size_t)j * 2048)     = ha;
                *(float4*)(Hrow + (size_t)j * 2048 + 4) = hb;
                if (lane == 31) { buf[j][0] = ha; buf[j][1] = hb; }
            }
        }
        __syncwarp();   // smem boundary-row visibility for next strip
    }
}

// ---------------- launch ----------------
extern "C" void kernel_launch(void* const* d_in, const int* in_sizes, int n_in,
                              void* d_out, int out_size) {
    const float* X    = (const float*)d_in[0];   // (128,128,16,64)
    const float* W    = (const float*)d_in[1];   // (64,128)
    const float* U    = (const float*)d_in[2];   // (2,128)
    const float* Bias = (const float*)d_in[3];   // (128,)
    float* H = (float*)d_out;                    // (128,128,16,128) — holds a, then h

    (void)in_sizes; (void)n_in; (void)out_size;

    mdrnn_gemm_kernel<<<2048, 256>>>(X, W, Bias, H);
    mdrnn_scan_kernel<<<256, 32>>>(U, H);
}

// round 7
// speedup vs baseline: 1.9274x; 1.9274x over previous
#include <cuda_runtime.h>
#include <cstdint>

// Problem dims
#define PD1   128
#define PD2   128
#define PB    16
#define PSIN  64
#define PSOUT 128
// a / h layout: [i][j][b][s] row-major, s fastest.
// float offset = i*262144 + j*2048 + b*128 + s

typedef unsigned long long ull_t;

__device__ __forceinline__ ull_t pack2(float x) {
    unsigned int xi = __float_as_uint(x);
    ull_t r;
    asm("mov.b64 %0, {%1, %1};" : "=l"(r) : "r"(xi));
    return r;
}
__device__ __forceinline__ void ffma2(ull_t &d, ull_t a, ull_t b) {
    asm("fma.rn.f32x2 %0, %1, %2, %0;" : "+l"(d) : "l"(a), "l"(b));
}
__device__ __forceinline__ float tanh_fast(float z) {
    // tanh(z) = 1 - 2/(exp(2z)+1) via MUFU ex2 + rcp (err ~1e-6)
    float e;
    asm("ex2.approx.f32 %0, %1;" : "=f"(e) : "f"(z * 2.8853900817779268f));
    float rc;
    asm("rcp.approx.f32 %0, %1;" : "=f"(rc) : "f"(e + 1.0f));
    return fmaf(-2.0f, rc, 1.0f);
}

// ---------------- Kernel 1: a = x @ w + bias  (into d_out) ----------------
// EXACT R2 version (measured ~96us): 128m x 128n tile, 256 threads,
// micro-tile 8m x 8n as 4 f32x2 segs, K=64 in two 32-wide phases.
#define XS_LD 36
__global__ __launch_bounds__(256)
void mdrnn_gemm_kernel(const float* __restrict__ X, const float* __restrict__ W,
                       const float* __restrict__ Bias, float* __restrict__ A) {
    __shared__ float xs[128 * XS_LD];   // 18432 B
    __shared__ float ws[32 * 128];      // 16384 B

    const int tid   = threadIdx.x;
    const int mtile = blockIdx.x;                 // 2048 tiles of 128 rows
    const float* Xb = X + (size_t)mtile * 128 * PSIN;

    const int tidm = tid >> 4;        // 0..15  -> m0 = tidm*8
    const int tidn = tid & 15;        // 0..15  -> n  = tidn*2 + seg*32
    const int m0   = tidm * 8;
    const int n0   = tidn * 2;

    ull_t acc[8][4];
#pragma unroll
    for (int mi = 0; mi < 8; mi++)
#pragma unroll
        for (int seg = 0; seg < 4; seg++) acc[mi][seg] = 0ULL;

    for (int kk = 0; kk < PSIN; kk += 32) {
        __syncthreads();
#pragma unroll
        for (int q = 0; q < 4; q++) {
            int id  = tid + 256 * q;
            int row = id >> 3;
            int kq  = id & 7;
            *(float4*)&xs[row * XS_LD + kq * 4] =
                *(const float4*)(Xb + row * PSIN + kk + kq * 4);
        }
#pragma unroll
        for (int q = 0; q < 4; q++) {
            int id = tid + 256 * q;
            int k  = id >> 5;
            int nq = id & 31;
            *(float4*)&ws[k * 128 + nq * 4] =
                *(const float4*)(W + (size_t)(kk + k) * PSOUT + nq * 4);
        }
        __syncthreads();

#pragma unroll 4
        for (int k = 0; k < 32; k++) {
            ull_t wv[4];
#pragma unroll
            for (int seg = 0; seg < 4; seg++)
                wv[seg] = *(const ull_t*)&ws[k * 128 + n0 + seg * 32];
#pragma unroll
            for (int mi = 0; mi < 8; mi++) {
                ull_t xp = pack2(xs[(m0 + mi) * XS_LD + k]);
#pragma unroll
                for (int seg = 0; seg < 4; seg++) ffma2(acc[mi][seg], xp, wv[seg]);
            }
        }
    }

    float2 bv[4];
#pragma unroll
    for (int seg = 0; seg < 4; seg++)
        bv[seg] = *(const float2*)(Bias + n0 + seg * 32);

#pragma unroll
    for (int mi = 0; mi < 8; mi++) {
        float* out = A + ((size_t)mtile * 128 + m0 + mi) * PSOUT;
#pragma unroll
        for (int seg = 0; seg < 4; seg++) {
            uint2 u = *(uint2*)&acc[mi][seg];
            float2 o;
            o.x = __uint_as_float(u.x) + bv[seg].x;
            o.y = __uint_as_float(u.y) + bv[seg].y;
            *(float2*)(out + n0 + seg * 32) = o;
        }
    }
}

// ---------------- Kernel 2: warp-synchronous wavefront scan ----------------
// 64 blocks x 128 threads = 4 warps/block, one (b, 8-s chunk) PER WARP
// (warps land on distinct SMSPs -> each warp owns its MUFU scheduler).
// Within a warp: rows on lanes (4 strips of 32), diagonal skew:
//   at iter t, lane l handles j = t - l; h[i-1][j] via __shfl_up of the
//   previous iteration's h. Strip boundary row via per-warp smem buf.
// Prefetch ring: SDEPTH=4 with #pragma unroll 4 -> STATIC indices (no
// local-mem demotion). Refill is activity-independent (guard only on jf).
#define SDEPTH 4
__global__ __launch_bounds__(128, 1)
void mdrnn_scan_kernel(const float* __restrict__ U, float* __restrict__ H) {
    __shared__ float4 buf[4][128][2];    // per-warp boundary rows, 16KB

    const int lane  = threadIdx.x & 31;
    const int warp  = threadIdx.x >> 5;          // 0..3
    const int chunk = blockIdx.x * 4 + warp;     // 0..255
    const int b     = chunk >> 4;                // 0..15
    const int sc    = chunk & 15;                // 0..15
    const int s0    = sc * 8;

    const float4 u0a = *(const float4*)(U + s0);
    const float4 u0b = *(const float4*)(U + s0 + 4);
    const float4 u1a = *(const float4*)(U + PSOUT + s0);
    const float4 u1b = *(const float4*)(U + PSOUT + s0 + 4);

    const size_t base_bs = (size_t)b * PSOUT + s0;

    for (int ss = 0; ss < 4; ss++) {
        const int row = ss * 32 + lane;
        float* Hrow = H + (size_t)row * 262144 + base_bs;   // + j*2048

        // seed: slot q <- a[j = q - lane] (consumed at t = q), valid j only
        float4 ra[SDEPTH], rb[SDEPTH];
#pragma unroll
        for (int q = 0; q < SDEPTH; q++) {
            int j = q - lane;
            if ((unsigned)j < 128u) {
                ra[q] = *(const float4*)(Hrow + (size_t)j * 2048);
                rb[q] = *(const float4*)(Hrow + (size_t)j * 2048 + 4);
            }
        }

        float4 ha = make_float4(0.f, 0.f, 0.f, 0.f);
        float4 hb = make_float4(0.f, 0.f, 0.f, 0.f);

#pragma unroll 4
        for (int t = 0; t < 160; t++) {
            // cross-lane handoff of previous iteration's h
            float4 pa, pb;
            pa.x = __shfl_up_sync(0xffffffffu, ha.x, 1);
            pa.y = __shfl_up_sync(0xffffffffu, ha.y, 1);
            pa.z = __shfl_up_sync(0xffffffffu, ha.z, 1);
            pa.w = __shfl_up_sync(0xffffffffu, ha.w, 1);
            pb.x = __shfl_up_sync(0xffffffffu, hb.x, 1);
            pb.y = __shfl_up_sync(0xffffffffu, hb.y, 1);
            pb.z = __shfl_up_sync(0xffffffffu, hb.z, 1);
            pb.w = __shfl_up_sync(0xffffffffu, hb.w, 1);

            const int j    = t - lane;
            const int slot = t & (SDEPTH - 1);   // static under unroll 4

            // consume slot, then refill (independent of this iter's activity)
            float4 aa = ra[slot], ab = rb[slot];
            int jf = t + SDEPTH - lane;
            if ((unsigned)jf < 128u) {
                ra[slot] = *(const float4*)(Hrow + (size_t)jf * 2048);
                rb[slot] = *(const float4*)(Hrow + (size_t)jf * 2048 + 4);
            }

            if ((unsigned)j < 128u) {
                float4 qa, qb;   // h[row-1][j]
                if (lane == 0) {
                    if (ss == 0) {
                        qa = make_float4(0.f, 0.f, 0.f, 0.f);
                        qb = make_float4(0.f, 0.f, 0.f, 0.f);
                    } else {
                        qa = buf[warp][j][0];
                        qb = buf[warp][j][1];
                    }
                } else {
                    qa = pa; qb = pb;
                }

                float4 za, zb;
                za.x = fmaf(qa.x, u0a.x, aa.x); za.x = fmaf(ha.x, u1a.x, za.x);
                za.y = fmaf(qa.y, u0a.y, aa.y); za.y = fmaf(ha.y, u1a.y, za.y);
                za.z = fmaf(qa.z, u0a.z, aa.z); za.z = fmaf(ha.z, u1a.z, za.z);
                za.w = fmaf(qa.w, u0a.w, aa.w); za.w = fmaf(ha.w, u1a.w, za.w);
                zb.x = fmaf(qb.x, u0b.x, ab.x); zb.x = fmaf(hb.x, u1b.x, zb.x);
                zb.y = fmaf(qb.y, u0b.y, ab.y); zb.y = fmaf(hb.y, u1b.y, zb.y);
                zb.z = fmaf(qb.z, u0b.z, ab.z); zb.z = fmaf(hb.z, u1b.z, zb.z);
                zb.w = fmaf(qb.w, u0b.w, ab.w); zb.w = fmaf(hb.w, u1b.w, zb.w);

                ha.x = tanh_fast(za.x); ha.y = tanh_fast(za.y);
                ha.z = tanh_fast(za.z); ha.w = tanh_fast(za.w);
                hb.x = tanh_fast(zb.x); hb.y = tanh_fast(zb.y);
                hb.z = tanh_fast(zb.z); hb.w = tanh_fast(zb.w);

                *(float4*)(Hrow + (size_t)j * 2048)     = ha;
                *(float4*)(Hrow + (size_t)j * 2048 + 4) = hb;
                if (lane == 31) { buf[warp][j][0] = ha; buf[warp][j][1] = hb; }
            }
        }
        __syncwarp();   // smem boundary-row visibility for next strip
    }
}

// ---------------- launch ----------------
extern "C" void kernel_launch(void* const* d_in, const int* in_sizes, int n_in,
                              void* d_out, int out_size) {
    const float* X    = (const float*)d_in[0];   // (128,128,16,64)
    const float* W    = (const float*)d_in[1];   // (64,128)
    const float* U    = (const float*)d_in[2];   // (2,128)
    const float* Bias = (const float*)d_in[3];   // (128,)
    float* H = (float*)d_out;                    // (128,128,16,128) — holds a, then h

    (void)in_sizes; (void)n_in; (void)out_size;

    mdrnn_gemm_kernel<<<2048, 256>>>(X, W, Bias, H);
    mdrnn_scan_kernel<<<64, 128>>>(U, H);
}